// round 10
// baseline (speedup 1.0000x reference)
#include <cuda_runtime.h>
#include <cuda_bf16.h>
#include <cstdint>

// Problem constants
#define NB  8
#define C   256
#define G   8
#define KPT 9
#define H   64
#define W   64
#define L   (H * W)          // 4096
#define CG  (C / G)          // 32
#define KA  512              // stored K: A=[hi|lo], B=[hi|lo]; GEMM runs K=768 via remap

// Scratch (static device memory)
__device__ float g_value[(size_t)NB * L * C];               // value proj (n,l,256) f32
__device__ float g_om_p[(size_t)NB * L * C];                // om padded (n,l,256) f32
__device__ __nv_bfloat16 g_aval[(size_t)NB * L * KA];       // A' for value GEMM
__device__ __nv_bfloat16 g_aom[(size_t)NB * L * KA];        // A' for om GEMM
__device__ __nv_bfloat16 g_aop[(size_t)NB * L * KA];        // A' for out GEMM
__device__ __nv_bfloat16 g_bw[3 * 256 * KA];                // B' weights (om, vp, op)
__device__ float g_bias_om[256];                            // padded om bias

// ---------------- small helpers ----------------
__device__ __forceinline__ uint32_t smem_u32(const void* p) {
    uint32_t a;
    asm("{ .reg .u64 t; cvta.to.shared.u64 t, %1; cvt.u32.u64 %0, t; }" : "=r"(a) : "l"(p));
    return a;
}
__device__ __forceinline__ void fma2(uint64_t& d, uint64_t a, uint64_t b) {
    asm("fma.rn.f32x2 %0, %1, %2, %0;" : "+l"(d) : "l"(a), "l"(b));
}
__device__ __forceinline__ uint64_t dup2(float a) {
    uint64_t r;
    asm("mov.b64 %0, {%1, %1};" : "=l"(r) : "f"(a));
    return r;
}
__device__ __forceinline__ float2 unpack2(uint64_t v) {
    float2 r;
    asm("mov.b64 {%0, %1}, %2;" : "=f"(r.x), "=f"(r.y) : "l"(v));
    return r;
}
__device__ __forceinline__ uint32_t packbf(__nv_bfloat16 lo, __nv_bfloat16 hi) {
    __nv_bfloat162 t;
    t.x = lo; t.y = hi;
    return *(uint32_t*)&t;
}
__device__ __forceinline__ void bsplit(float v, __nv_bfloat16& h, __nv_bfloat16& l) {
    h = __float2bfloat16(v);
    l = __float2bfloat16(v - __bfloat162float(h));
}

// ---- warp mma primitives (sm_80-compatible; legal under compute_103) ------
__device__ __forceinline__ void ldmatrix_x4(uint32_t& r0, uint32_t& r1,
                                            uint32_t& r2, uint32_t& r3,
                                            uint32_t addr) {
    asm volatile("ldmatrix.sync.aligned.m8n8.x4.shared.b16 {%0,%1,%2,%3}, [%4];"
                 : "=r"(r0), "=r"(r1), "=r"(r2), "=r"(r3) : "r"(addr));
}
__device__ __forceinline__ void mma16816(float* d, const uint32_t* a,
                                         const uint32_t* b) {
    asm volatile(
        "mma.sync.aligned.m16n8k16.row.col.f32.bf16.bf16.f32 "
        "{%0,%1,%2,%3}, {%4,%5,%6,%7}, {%8,%9}, {%0,%1,%2,%3};"
        : "+f"(d[0]), "+f"(d[1]), "+f"(d[2]), "+f"(d[3])
        : "r"(a[0]), "r"(a[1]), "r"(a[2]), "r"(a[3]), "r"(b[0]), "r"(b[1]));
}
__device__ __forceinline__ void cp16(uint32_t saddr, const void* g) {
    asm volatile("cp.async.cg.shared.global [%0], [%1], 16;" :: "r"(saddr), "l"(g));
}
__device__ __forceinline__ void cp_commit() {
    asm volatile("cp.async.commit_group;" ::: "memory");
}
template <int N>
__device__ __forceinline__ void cp_wait() {
    asm volatile("cp.async.wait_group %0;" :: "n"(N) : "memory");
}

// ---------------------------------------------------------------------------
// Weight prep: Wsrc (J,256) f32 -> B' (256 rows, 512) bf16 [hi | lo]
// ---------------------------------------------------------------------------
__global__ __launch_bounds__(256) void prep_w_kernel(const float* __restrict__ om_w,
                                                     const float* __restrict__ om_b,
                                                     const float* __restrict__ vp_w,
                                                     const float* __restrict__ op_w) {
    int j = blockIdx.x;
    int ws = blockIdx.y;
    int c = threadIdx.x;
    const float* Wsrc = (ws == 0) ? om_w : (ws == 1) ? vp_w : op_w;
    int Jrows = (ws == 0) ? 216 : 256;
    float v = (j < Jrows) ? Wsrc[j * 256 + c] : 0.f;
    __nv_bfloat16 h, lo;
    bsplit(v, h, lo);
    __nv_bfloat16* outw = g_bw + ((size_t)ws * 256 + j) * KA;
    outw[c] = h;
    outw[256 + c] = lo;
    if (ws == 0 && j == 0)
        g_bias_om[c] = (c < 216) ? om_b[c] : 0.f;
}

// ---------------------------------------------------------------------------
// Transpose-convert: X (n, 256, L) f32 -> A' (n, L, 512) bf16 [hi | lo]
// grid (L/256, 4, NB)
// ---------------------------------------------------------------------------
__global__ __launch_bounds__(256) void convT_kernel(const float* __restrict__ X,
                                                    __nv_bfloat16* __restrict__ Ab) {
    int l = blockIdx.x * 256 + threadIdx.x;
    int c80 = blockIdx.y * 8;
    int n = blockIdx.z;
    const float* xp = X + ((size_t)n * 256) * L + l;
    char* ob = (char*)(Ab + ((size_t)(n * L + l)) * KA);
#pragma unroll
    for (int c8 = c80; c8 < c80 + 8; c8++) {
        uint32_t hi[4], lw[4];
#pragma unroll
        for (int j = 0; j < 4; j++) {
            float a = xp[(size_t)(c8 * 8 + 2 * j) * L];
            float b = xp[(size_t)(c8 * 8 + 2 * j + 1) * L];
            __nv_bfloat16 ha, la, hb, lb;
            bsplit(a, ha, la);
            bsplit(b, hb, lb);
            hi[j] = packbf(ha, hb);
            lw[j] = packbf(la, lb);
        }
        *(uint4*)(ob + c8 * 16)       = make_uint4(hi[0], hi[1], hi[2], hi[3]);
        *(uint4*)(ob + 512 + c8 * 16) = make_uint4(lw[0], lw[1], lw[2], lw[3]);
    }
}

// ---------------------------------------------------------------------------
// Fused depthwise-conv + transpose-convert for the om path.
// grid (L/256, 4, NB)
// ---------------------------------------------------------------------------
__global__ __launch_bounds__(256) void convT_om_kernel(const float* __restrict__ x,
                                                       const float* __restrict__ dw,
                                                       const float* __restrict__ db,
                                                       __nv_bfloat16* __restrict__ Ab) {
    int l = blockIdx.x * 256 + threadIdx.x;
    int c80 = blockIdx.y * 8;
    int n = blockIdx.z;
    int yy = l >> 6, xx = l & 63;

    int offs[9];
    float val9[9];
#pragma unroll
    for (int t = 0; t < 9; t++) {
        int dy = t / 3 - 1, dx = t % 3 - 1;
        int y2 = yy + dy, x2 = xx + dx;
        bool v = (y2 >= 0 && y2 < H && x2 >= 0 && x2 < W);
        offs[t] = v ? (y2 * W + x2) : 0;
        val9[t] = v ? 1.f : 0.f;
    }

    const float* xb = x + ((size_t)n * 256) * L;
    char* ob = (char*)(Ab + ((size_t)(n * L + l)) * KA);

#pragma unroll
    for (int c8 = c80; c8 < c80 + 8; c8++) {
        uint32_t hi[4], lw[4];
#pragma unroll
        for (int j = 0; j < 4; j++) {
            float r[2];
#pragma unroll
            for (int s = 0; s < 2; s++) {
                int c = c8 * 8 + 2 * j + s;
                const float* xc = xb + (size_t)c * L;
                const float* wc = dw + c * 9;
                float acc = db[c];
#pragma unroll
                for (int t = 0; t < 9; t++)
                    acc += wc[t] * val9[t] * xc[offs[t]];
                r[s] = acc;
            }
            __nv_bfloat16 ha, la, hb, lb;
            bsplit(r[0], ha, la);
            bsplit(r[1], hb, lb);
            hi[j] = packbf(ha, hb);
            lw[j] = packbf(la, lb);
        }
        *(uint4*)(ob + c8 * 16)       = make_uint4(hi[0], hi[1], hi[2], hi[3]);
        *(uint4*)(ob + 512 + c8 * 16) = make_uint4(lw[0], lw[1], lw[2], lw[3]);
    }
}

// ---------------------------------------------------------------------------
// Warp-mma bf16 GEMM, v2: 4 warps, 64x64 warp tiles, 3-stage cp.async.
// Split remap: storage K=512; logical K=768:
//   kc<8: ah*bh | 8..15: al*bh | 16..23: ah*bl.
// mode 0: out row-major (n, L, 256) f32 + bias;  mode 1: NCHW, no bias.
// ---------------------------------------------------------------------------
#define BK 32
#define ASTR 40              // padded smem row stride (bf16 units)
#define NKC 24
#define STG 3
#define TILEB (128 * ASTR * 2)           // 10240 B per tile
#define SMEM_GEMM (STG * 2 * TILEB)      // 61440 B

__device__ __forceinline__ int a_seg(int kc) {
    return (kc < 8) ? kc * BK : (kc < 16) ? 256 + (kc - 8) * BK : (kc - 16) * BK;
}
__device__ __forceinline__ int b_seg(int kc) {
    return (kc < 16) ? (kc & 7) * BK : 256 + (kc - 16) * BK;
}

__global__ __launch_bounds__(128)
void gemm_mma_kernel(const __nv_bfloat16* __restrict__ Ab,
                     const __nv_bfloat16* __restrict__ Bb,
                     const float* __restrict__ bias,
                     float* __restrict__ outp,
                     int mode) {
    extern __shared__ char sm[];
    uint32_t s0 = smem_u32(sm);

    int tid = threadIdx.x;
    int lane = tid & 31;
    int wid = tid >> 5;
    int warp_m = wid >> 1;       // 0..1
    int warp_n = wid & 1;        // 0..1
    int n0 = blockIdx.x * 128;
    int m0 = blockIdx.y * 128;
    int n  = blockIdx.z;

    const __nv_bfloat16* Ag = Ab + ((size_t)(n * L + m0) + tid) * KA;
    const __nv_bfloat16* Bg = Bb + ((size_t)n0 + tid) * KA;

    // per-stage smem tile bases (bytes)
    uint32_t sA[STG], sB[STG];
#pragma unroll
    for (int s = 0; s < STG; s++) {
        sA[s] = s0 + s * TILEB;
        sB[s] = s0 + STG * TILEB + s * TILEB;
    }
    uint32_t srow = tid * (ASTR * 2);   // this thread's row offset in a tile

    float d[4][8][4];
#pragma unroll
    for (int i = 0; i < 4; i++)
#pragma unroll
        for (int j = 0; j < 8; j++)
#pragma unroll
            for (int k = 0; k < 4; k++) d[i][j][k] = 0.f;

    // issue stage loads for chunk kc into stage buffer s
    auto issue = [&](int kc, int s) {
        int ao = a_seg(kc), bo = b_seg(kc);
        const char* ga = (const char*)(Ag + ao);
        const char* gb = (const char*)(Bg + bo);
#pragma unroll
        for (int i = 0; i < 4; i++) {
            cp16(sA[s] + srow + i * 16, ga + i * 16);
            cp16(sB[s] + srow + i * 16, gb + i * 16);
        }
        cp_commit();
    };

    issue(0, 0);
    issue(1, 1);

    int a_rbase = warp_m * 64 + (lane & 15);
    int a_kbase = (lane >> 4) << 3;
    int b_rbase = warp_n * 64 + (((lane >> 4) & 1) << 3) + (lane & 7);
    int b_kbase = ((lane >> 3) & 1) << 3;

    for (int kc = 0; kc < NKC; kc++) {
        cp_wait<1>();
        __syncthreads();
        int buf = kc % STG;
        if (kc + 2 < NKC) issue(kc + 2, (kc + 2) % STG);

#pragma unroll
        for (int kk = 0; kk < 2; kk++) {
            uint32_t b[8][2];
#pragma unroll
            for (int ntp = 0; ntp < 4; ntp++) {
                uint32_t addr = sB[buf] +
                    ((b_rbase + ntp * 16) * ASTR + kk * 16 + b_kbase) * 2;
                ldmatrix_x4(b[2 * ntp][0], b[2 * ntp][1],
                            b[2 * ntp + 1][0], b[2 * ntp + 1][1], addr);
            }
#pragma unroll
            for (int mt = 0; mt < 4; mt++) {
                uint32_t a[4];
                uint32_t addr = sA[buf] +
                    ((a_rbase + mt * 16) * ASTR + kk * 16 + a_kbase) * 2;
                ldmatrix_x4(a[0], a[1], a[2], a[3], addr);
#pragma unroll
                for (int nt = 0; nt < 8; nt++)
                    mma16816(d[mt][nt], a, b[nt]);
            }
        }
        __syncthreads();
    }

    // epilogue
    int rbase = m0 + warp_m * 64 + (lane >> 2);
    int cbase = n0 + warp_n * 64 + (lane & 3) * 2;
    if (mode == 0) {
        float* ob = outp + (size_t)n * L * 256;
#pragma unroll
        for (int mt = 0; mt < 4; mt++) {
#pragma unroll
            for (int nt = 0; nt < 8; nt++) {
                int r = rbase + mt * 16;
                int c = cbase + nt * 8;
                float bx = __ldg(bias + c), by = __ldg(bias + c + 1);
                *(float2*)(ob + (size_t)r * 256 + c) =
                    make_float2(d[mt][nt][0] + bx, d[mt][nt][1] + by);
                *(float2*)(ob + (size_t)(r + 8) * 256 + c) =
                    make_float2(d[mt][nt][2] + bx, d[mt][nt][3] + by);
            }
        }
    } else {
        float* ob = outp + (size_t)n * 256 * L;
#pragma unroll
        for (int mt = 0; mt < 4; mt++) {
#pragma unroll
            for (int nt = 0; nt < 8; nt++) {
                int r = rbase + mt * 16;
                int c = cbase + nt * 8;
                float* p0 = ob + (size_t)c * L;
                float* p1 = ob + (size_t)(c + 1) * L;
                p0[r] = d[mt][nt][0];
                p1[r] = d[mt][nt][1];
                p0[r + 8] = d[mt][nt][2];
                p1[r + 8] = d[mt][nt][3];
            }
        }
    }
}

// ---------------------------------------------------------------------------
// Deformable bilinear sampling; emits split-bf16 A' [hi | lo] for out GEMM.
// ---------------------------------------------------------------------------
__global__ __launch_bounds__(256) void sample_kernel() {
    __shared__ float om_s[32][28];

    int tid = threadIdx.x;
    int c4 = tid & 7;
    int li = tid >> 3;
    int l0 = blockIdx.x * 32;
    int g  = blockIdx.y;
    int n  = blockIdx.z;

    for (int i = tid; i < 32 * 27; i += 256) {
        int li2 = i / 27, j = i - li2 * 27;
        om_s[li2][j] = g_om_p[(size_t)(n * L + l0 + li2) * 256 + g * 27 + j];
    }
    __syncthreads();

    int l = l0 + li;
    int yy = l >> 6, xx = l & 63;

    const ulonglong2* __restrict__ vp =
        (const ulonglong2*)(g_value + (size_t)n * L * C + g * CG) + c4;
    const float fyy = (float)yy, fxx = (float)xx;

    uint64_t acc0 = 0ull, acc1 = 0ull;

#pragma unroll
    for (int k = 0; k < KPT; k++) {
        float oy = om_s[li][2 * k];
        float ox = om_s[li][2 * k + 1];
        float mw = om_s[li][18 + k];

        float py = fyy + (float)(k / 3 - 1) + oy;
        float px = fxx + (float)(k % 3 - 1) + ox;
        float y0f = floorf(py), x0f = floorf(px);
        float tyf = py - y0f, txf = px - x0f;
        int y0 = (int)y0f, x0 = (int)x0f;
        int y1 = y0 + 1, x1 = x0 + 1;

        float vy0 = (y0 >= 0 && y0 < H) ? 1.f : 0.f;
        float vy1 = (y1 >= 0 && y1 < H) ? 1.f : 0.f;
        float vx0 = (x0 >= 0 && x0 < W) ? 1.f : 0.f;
        float vx1 = (x1 >= 0 && x1 < W) ? 1.f : 0.f;

        float w00 = mw * (1.f - tyf) * (1.f - txf) * vy0 * vx0;
        float w01 = mw * (1.f - tyf) * txf * vy0 * vx1;
        float w10 = mw * tyf * (1.f - txf) * vy1 * vx0;
        float w11 = mw * tyf * txf * vy1 * vx1;

        int y0c = min(max(y0, 0), H - 1);
        int y1c = min(max(y1, 0), H - 1);
        int x0c = min(max(x0, 0), W - 1);
        int x1c = min(max(x1, 0), W - 1);

        int yA = y0c << 12, yB = y1c << 12;
        int xA = x0c << 6,  xB = x1c << 6;

        ulonglong2 v00 = __ldg(vp + (yA + xA));
        ulonglong2 v01 = __ldg(vp + (yA + xB));
        ulonglong2 v10 = __ldg(vp + (yB + xA));
        ulonglong2 v11 = __ldg(vp + (yB + xB));

        uint64_t w00p = dup2(w00), w01p = dup2(w01);
        uint64_t w10p = dup2(w10), w11p = dup2(w11);

        fma2(acc0, w00p, v00.x);
        fma2(acc1, w00p, v00.y);
        fma2(acc0, w01p, v01.x);
        fma2(acc1, w01p, v01.y);
        fma2(acc0, w10p, v10.x);
        fma2(acc1, w10p, v10.y);
        fma2(acc0, w11p, v11.x);
        fma2(acc1, w11p, v11.y);
    }

    float2 a01 = unpack2(acc0);
    float2 a23 = unpack2(acc1);
    __nv_bfloat16 h0, l0b, h1, l1b, h2, l2b, h3, l3b;
    bsplit(a01.x, h0, l0b);
    bsplit(a01.y, h1, l1b);
    bsplit(a23.x, h2, l2b);
    bsplit(a23.y, h3, l3b);
    uint2 hv = make_uint2(packbf(h0, h1), packbf(h2, h3));
    uint2 lv = make_uint2(packbf(l0b, l1b), packbf(l2b, l3b));

    char* ob = (char*)(g_aop + ((size_t)(n * L + l)) * KA) + (g * 32 + c4 * 4) * 2;
    *(uint2*)(ob)       = hv;     // hi @ elems [0,256)
    *(uint2*)(ob + 512) = lv;     // lo @ elems [256,512)
}

// ---------------------------------------------------------------------------
// Launch
// ---------------------------------------------------------------------------
extern "C" void kernel_launch(void* const* d_in, const int* in_sizes, int n_in,
                              void* d_out, int out_size) {
    const float* x    = (const float*)d_in[0];
    const float* dw_w = (const float*)d_in[1];
    const float* dw_b = (const float*)d_in[2];
    const float* om_w = (const float*)d_in[3];
    const float* om_b = (const float*)d_in[4];
    const float* vp_w = (const float*)d_in[5];
    const float* vp_b = (const float*)d_in[6];
    const float* op_w = (const float*)d_in[7];
    float* out = (float*)d_out;

    float *p_value, *p_om_p, *p_bias_om;
    __nv_bfloat16 *p_aval, *p_aom, *p_aop, *p_bw;
    cudaGetSymbolAddress((void**)&p_value, g_value);
    cudaGetSymbolAddress((void**)&p_om_p, g_om_p);
    cudaGetSymbolAddress((void**)&p_bias_om, g_bias_om);
    cudaGetSymbolAddress((void**)&p_aval, g_aval);
    cudaGetSymbolAddress((void**)&p_aom, g_aom);
    cudaGetSymbolAddress((void**)&p_aop, g_aop);
    cudaGetSymbolAddress((void**)&p_bw, g_bw);

    cudaFuncSetAttribute(gemm_mma_kernel,
                         cudaFuncAttributeMaxDynamicSharedMemorySize, SMEM_GEMM);

    prep_w_kernel<<<dim3(256, 3), 256>>>(om_w, om_b, vp_w, op_w);
    convT_kernel<<<dim3(L / 256, 4, NB), 256>>>(x, p_aval);
    convT_om_kernel<<<dim3(L / 256, 4, NB), 256>>>(x, dw_w, dw_b, p_aom);
    gemm_mma_kernel<<<dim3(2, 32, NB), 128, SMEM_GEMM>>>(p_aom, p_bw, p_bias_om, p_om_p, 0);
    gemm_mma_kernel<<<dim3(2, 32, NB), 128, SMEM_GEMM>>>(p_aval, p_bw + (size_t)256 * KA, vp_b, p_value, 0);
    sample_kernel<<<dim3(L / 32, G, NB), 256>>>();
    gemm_mma_kernel<<<dim3(2, 32, NB), 128, SMEM_GEMM>>>(p_aop, p_bw + (size_t)2 * 256 * KA, p_bias_om, out, 1);
}

// round 12
// speedup vs baseline: 1.0339x; 1.0339x over previous
#include <cuda_runtime.h>
#include <cuda_bf16.h>
#include <cstdint>

// Problem constants
#define NB  8
#define C   256
#define G   8
#define KPT 9
#define H   64
#define W   64
#define L   (H * W)          // 4096
#define CG  (C / G)          // 32
#define KA  512              // stored K: A=[hi|lo], B=[hi|lo]; GEMM runs K=768 via remap

// Scratch (static device memory)
__device__ float g_value[(size_t)NB * L * C];               // value proj (n,l,256) f32
__device__ float g_om_p[(size_t)NB * L * C];                // om padded (n,l,256) f32
__device__ __nv_bfloat16 g_aval[(size_t)NB * L * KA];       // A' for value GEMM
__device__ __nv_bfloat16 g_aom[(size_t)NB * L * KA];        // A' for om GEMM
__device__ __nv_bfloat16 g_aop[(size_t)NB * L * KA];        // A' for out GEMM
__device__ __nv_bfloat16 g_bw[3 * 256 * KA];                // B' weights (om, vp, op)
__device__ float g_bias_om[256];                            // padded om bias

// ---------------- small helpers ----------------
__device__ __forceinline__ uint32_t smem_u32(const void* p) {
    uint32_t a;
    asm("{ .reg .u64 t; cvta.to.shared.u64 t, %1; cvt.u32.u64 %0, t; }" : "=r"(a) : "l"(p));
    return a;
}
__device__ __forceinline__ void fma2(uint64_t& d, uint64_t a, uint64_t b) {
    asm("fma.rn.f32x2 %0, %1, %2, %0;" : "+l"(d) : "l"(a), "l"(b));
}
__device__ __forceinline__ uint64_t dup2(float a) {
    uint64_t r;
    asm("mov.b64 %0, {%1, %1};" : "=l"(r) : "f"(a));
    return r;
}
__device__ __forceinline__ float2 unpack2(uint64_t v) {
    float2 r;
    asm("mov.b64 {%0, %1}, %2;" : "=f"(r.x), "=f"(r.y) : "l"(v));
    return r;
}
__device__ __forceinline__ uint32_t packbf(__nv_bfloat16 lo, __nv_bfloat16 hi) {
    __nv_bfloat162 t;
    t.x = lo; t.y = hi;
    return *(uint32_t*)&t;
}
__device__ __forceinline__ void bsplit(float v, __nv_bfloat16& h, __nv_bfloat16& l) {
    h = __float2bfloat16(v);
    l = __float2bfloat16(v - __bfloat162float(h));
}

// ---- warp mma primitives (sm_80-compatible; legal under compute_103) ------
__device__ __forceinline__ void ldmatrix_x4(uint32_t& r0, uint32_t& r1,
                                            uint32_t& r2, uint32_t& r3,
                                            uint32_t addr) {
    asm volatile("ldmatrix.sync.aligned.m8n8.x4.shared.b16 {%0,%1,%2,%3}, [%4];"
                 : "=r"(r0), "=r"(r1), "=r"(r2), "=r"(r3) : "r"(addr));
}
__device__ __forceinline__ void mma16816(float* d, const uint32_t* a,
                                         const uint32_t* b) {
    asm volatile(
        "mma.sync.aligned.m16n8k16.row.col.f32.bf16.bf16.f32 "
        "{%0,%1,%2,%3}, {%4,%5,%6,%7}, {%8,%9}, {%0,%1,%2,%3};"
        : "+f"(d[0]), "+f"(d[1]), "+f"(d[2]), "+f"(d[3])
        : "r"(a[0]), "r"(a[1]), "r"(a[2]), "r"(a[3]), "r"(b[0]), "r"(b[1]));
}
__device__ __forceinline__ void cp16(uint32_t saddr, const void* g) {
    asm volatile("cp.async.cg.shared.global [%0], [%1], 16;" :: "r"(saddr), "l"(g));
}
__device__ __forceinline__ void cp_commit() {
    asm volatile("cp.async.commit_group;" ::: "memory");
}
template <int N>
__device__ __forceinline__ void cp_wait() {
    asm volatile("cp.async.wait_group %0;" :: "n"(N) : "memory");
}

// ---------------------------------------------------------------------------
// Weight prep: Wsrc (J,256) f32 -> B' (256 rows, 512) bf16 [hi | lo]
// ---------------------------------------------------------------------------
__global__ __launch_bounds__(256) void prep_w_kernel(const float* __restrict__ om_w,
                                                     const float* __restrict__ om_b,
                                                     const float* __restrict__ vp_w,
                                                     const float* __restrict__ op_w) {
    int j = blockIdx.x;
    int ws = blockIdx.y;
    int c = threadIdx.x;
    const float* Wsrc = (ws == 0) ? om_w : (ws == 1) ? vp_w : op_w;
    int Jrows = (ws == 0) ? 216 : 256;
    float v = (j < Jrows) ? Wsrc[j * 256 + c] : 0.f;
    __nv_bfloat16 h, lo;
    bsplit(v, h, lo);
    __nv_bfloat16* outw = g_bw + ((size_t)ws * 256 + j) * KA;
    outw[c] = h;
    outw[256 + c] = lo;
    if (ws == 0 && j == 0)
        g_bias_om[c] = (c < 216) ? om_b[c] : 0.f;
}

// ---------------------------------------------------------------------------
// Transpose-convert: X (n, 256, L) f32 -> A' (n, L, 512) bf16 [hi | lo]
// grid (L/256, 4, NB)
// ---------------------------------------------------------------------------
__global__ __launch_bounds__(256) void convT_kernel(const float* __restrict__ X,
                                                    __nv_bfloat16* __restrict__ Ab) {
    int l = blockIdx.x * 256 + threadIdx.x;
    int c80 = blockIdx.y * 8;
    int n = blockIdx.z;
    const float* xp = X + ((size_t)n * 256) * L + l;
    char* ob = (char*)(Ab + ((size_t)(n * L + l)) * KA);
#pragma unroll
    for (int c8 = c80; c8 < c80 + 8; c8++) {
        uint32_t hi[4], lw[4];
#pragma unroll
        for (int j = 0; j < 4; j++) {
            float a = xp[(size_t)(c8 * 8 + 2 * j) * L];
            float b = xp[(size_t)(c8 * 8 + 2 * j + 1) * L];
            __nv_bfloat16 ha, la, hb, lb;
            bsplit(a, ha, la);
            bsplit(b, hb, lb);
            hi[j] = packbf(ha, hb);
            lw[j] = packbf(la, lb);
        }
        *(uint4*)(ob + c8 * 16)       = make_uint4(hi[0], hi[1], hi[2], hi[3]);
        *(uint4*)(ob + 512 + c8 * 16) = make_uint4(lw[0], lw[1], lw[2], lw[3]);
    }
}

// ---------------------------------------------------------------------------
// Fused depthwise-conv + transpose-convert for the om path.
// grid (L/256, 4, NB)
// ---------------------------------------------------------------------------
__global__ __launch_bounds__(256) void convT_om_kernel(const float* __restrict__ x,
                                                       const float* __restrict__ dw,
                                                       const float* __restrict__ db,
                                                       __nv_bfloat16* __restrict__ Ab) {
    int l = blockIdx.x * 256 + threadIdx.x;
    int c80 = blockIdx.y * 8;
    int n = blockIdx.z;
    int yy = l >> 6, xx = l & 63;

    int offs[9];
    float val9[9];
#pragma unroll
    for (int t = 0; t < 9; t++) {
        int dy = t / 3 - 1, dx = t % 3 - 1;
        int y2 = yy + dy, x2 = xx + dx;
        bool v = (y2 >= 0 && y2 < H && x2 >= 0 && x2 < W);
        offs[t] = v ? (y2 * W + x2) : 0;
        val9[t] = v ? 1.f : 0.f;
    }

    const float* xb = x + ((size_t)n * 256) * L;
    char* ob = (char*)(Ab + ((size_t)(n * L + l)) * KA);

#pragma unroll
    for (int c8 = c80; c8 < c80 + 8; c8++) {
        uint32_t hi[4], lw[4];
#pragma unroll
        for (int j = 0; j < 4; j++) {
            float r[2];
#pragma unroll
            for (int s = 0; s < 2; s++) {
                int c = c8 * 8 + 2 * j + s;
                const float* xc = xb + (size_t)c * L;
                const float* wc = dw + c * 9;
                float acc = db[c];
#pragma unroll
                for (int t = 0; t < 9; t++)
                    acc += wc[t] * val9[t] * xc[offs[t]];
                r[s] = acc;
            }
            __nv_bfloat16 ha, la, hb, lb;
            bsplit(r[0], ha, la);
            bsplit(r[1], hb, lb);
            hi[j] = packbf(ha, hb);
            lw[j] = packbf(la, lb);
        }
        *(uint4*)(ob + c8 * 16)       = make_uint4(hi[0], hi[1], hi[2], hi[3]);
        *(uint4*)(ob + 512 + c8 * 16) = make_uint4(lw[0], lw[1], lw[2], lw[3]);
    }
}

// ---------------------------------------------------------------------------
// Warp-mma bf16 GEMM, v3: 8 warps (2m x 4n of 64x64), CTA 128x256 (full N),
// 3-stage cp.async. Split remap: storage K=512; logical K=768:
//   kc<8: ah*bh | 8..15: al*bh | 16..23: ah*bl.
// grid (1, L/128, NB).
// mode 0: out row-major (n, L, 256) f32 + bias;  mode 1: NCHW, no bias.
// ---------------------------------------------------------------------------
#define BK 32
#define ASTR 40              // padded smem row stride (bf16 units)
#define NKC 24
#define STG 3
#define ATILE (128 * ASTR * 2)           // 10240 B
#define BTILE (256 * ASTR * 2)           // 20480 B
#define SMEM_GEMM (STG * (ATILE + BTILE))  // 92160 B

__device__ __forceinline__ int a_seg(int kc) {
    return (kc < 8) ? kc * BK : (kc < 16) ? 256 + (kc - 8) * BK : (kc - 16) * BK;
}
__device__ __forceinline__ int b_seg(int kc) {
    return (kc < 16) ? (kc & 7) * BK : 256 + (kc - 16) * BK;
}

__global__ __launch_bounds__(256)
void gemm_mma_kernel(const __nv_bfloat16* __restrict__ Ab,
                     const __nv_bfloat16* __restrict__ Bb,
                     const float* __restrict__ bias,
                     float* __restrict__ outp,
                     int mode) {
    extern __shared__ char sm[];
    uint32_t s0 = smem_u32(sm);

    int tid = threadIdx.x;
    int lane = tid & 31;
    int wid = tid >> 5;
    int warp_m = wid >> 2;       // 0..1
    int warp_n = wid & 3;        // 0..3
    int m0 = blockIdx.y * 128;
    int n  = blockIdx.z;

    // A loader mapping: row = tid>>1 (128 rows), 32B seg = (tid&1)*32
    const char* AgL = (const char*)(Ab + ((size_t)(n * L + m0) + (tid >> 1)) * KA) + (tid & 1) * 32;
    // B loader mapping: row = tid (256 rows), 4x16B
    const char* BgL = (const char*)(Bb + ((size_t)tid) * KA);

    uint32_t sA[STG], sB[STG];
#pragma unroll
    for (int s = 0; s < STG; s++) {
        sA[s] = s0 + s * ATILE;
        sB[s] = s0 + STG * ATILE + s * BTILE;
    }
    uint32_t sArow = (tid >> 1) * (ASTR * 2) + (tid & 1) * 32;
    uint32_t sBrow = tid * (ASTR * 2);

    float d[4][8][4];
#pragma unroll
    for (int i = 0; i < 4; i++)
#pragma unroll
        for (int j = 0; j < 8; j++)
#pragma unroll
            for (int k = 0; k < 4; k++) d[i][j][k] = 0.f;

    auto issue = [&](int kc, int s) {
        int ao = a_seg(kc) * 2, bo = b_seg(kc) * 2;   // byte offsets
        cp16(sA[s] + sArow,      AgL + ao);
        cp16(sA[s] + sArow + 16, AgL + ao + 16);
#pragma unroll
        for (int i = 0; i < 4; i++)
            cp16(sB[s] + sBrow + i * 16, BgL + bo + i * 16);
        cp_commit();
    };

    issue(0, 0);
    issue(1, 1);

    int a_rbase = warp_m * 64 + (lane & 15);
    int a_kbase = (lane >> 4) << 3;
    int b_rbase = warp_n * 64 + (((lane >> 4) & 1) << 3) + (lane & 7);
    int b_kbase = ((lane >> 3) & 1) << 3;

    for (int kc = 0; kc < NKC; kc++) {
        cp_wait<1>();
        __syncthreads();
        int buf = kc % STG;
        if (kc + 2 < NKC) issue(kc + 2, (kc + 2) % STG);

#pragma unroll
        for (int kk = 0; kk < 2; kk++) {
            uint32_t b[8][2];
#pragma unroll
            for (int ntp = 0; ntp < 4; ntp++) {
                uint32_t addr = sB[buf] +
                    ((b_rbase + ntp * 16) * ASTR + kk * 16 + b_kbase) * 2;
                ldmatrix_x4(b[2 * ntp][0], b[2 * ntp][1],
                            b[2 * ntp + 1][0], b[2 * ntp + 1][1], addr);
            }
#pragma unroll
            for (int mt = 0; mt < 4; mt++) {
                uint32_t a[4];
                uint32_t addr = sA[buf] +
                    ((a_rbase + mt * 16) * ASTR + kk * 16 + a_kbase) * 2;
                ldmatrix_x4(a[0], a[1], a[2], a[3], addr);
#pragma unroll
                for (int nt = 0; nt < 8; nt++)
                    mma16816(d[mt][nt], a, b[nt]);
            }
        }
        __syncthreads();
    }

    // epilogue
    int rbase = m0 + warp_m * 64 + (lane >> 2);
    int cbase = warp_n * 64 + (lane & 3) * 2;
    if (mode == 0) {
        float* ob = outp + (size_t)n * L * 256;
#pragma unroll
        for (int mt = 0; mt < 4; mt++) {
#pragma unroll
            for (int nt = 0; nt < 8; nt++) {
                int r = rbase + mt * 16;
                int c = cbase + nt * 8;
                float bx = __ldg(bias + c), by = __ldg(bias + c + 1);
                *(float2*)(ob + (size_t)r * 256 + c) =
                    make_float2(d[mt][nt][0] + bx, d[mt][nt][1] + by);
                *(float2*)(ob + (size_t)(r + 8) * 256 + c) =
                    make_float2(d[mt][nt][2] + bx, d[mt][nt][3] + by);
            }
        }
    } else {
        float* ob = outp + (size_t)n * 256 * L;
#pragma unroll
        for (int mt = 0; mt < 4; mt++) {
#pragma unroll
            for (int nt = 0; nt < 8; nt++) {
                int r = rbase + mt * 16;
                int c = cbase + nt * 8;
                float* p0 = ob + (size_t)c * L;
                float* p1 = ob + (size_t)(c + 1) * L;
                p0[r] = d[mt][nt][0];
                p1[r] = d[mt][nt][1];
                p0[r + 8] = d[mt][nt][2];
                p1[r + 8] = d[mt][nt][3];
            }
        }
    }
}

// ---------------------------------------------------------------------------
// Deformable bilinear sampling; emits split-bf16 A' [hi | lo] for out GEMM.
// ---------------------------------------------------------------------------
__global__ __launch_bounds__(256) void sample_kernel() {
    __shared__ float om_s[32][28];

    int tid = threadIdx.x;
    int c4 = tid & 7;
    int li = tid >> 3;
    int l0 = blockIdx.x * 32;
    int g  = blockIdx.y;
    int n  = blockIdx.z;

    for (int i = tid; i < 32 * 27; i += 256) {
        int li2 = i / 27, j = i - li2 * 27;
        om_s[li2][j] = g_om_p[(size_t)(n * L + l0 + li2) * 256 + g * 27 + j];
    }
    __syncthreads();

    int l = l0 + li;
    int yy = l >> 6, xx = l & 63;

    const ulonglong2* __restrict__ vp =
        (const ulonglong2*)(g_value + (size_t)n * L * C + g * CG) + c4;
    const float fyy = (float)yy, fxx = (float)xx;

    uint64_t acc0 = 0ull, acc1 = 0ull;

#pragma unroll
    for (int k = 0; k < KPT; k++) {
        float oy = om_s[li][2 * k];
        float ox = om_s[li][2 * k + 1];
        float mw = om_s[li][18 + k];

        float py = fyy + (float)(k / 3 - 1) + oy;
        float px = fxx + (float)(k % 3 - 1) + ox;
        float y0f = floorf(py), x0f = floorf(px);
        float tyf = py - y0f, txf = px - x0f;
        int y0 = (int)y0f, x0 = (int)x0f;
        int y1 = y0 + 1, x1 = x0 + 1;

        float vy0 = (y0 >= 0 && y0 < H) ? 1.f : 0.f;
        float vy1 = (y1 >= 0 && y1 < H) ? 1.f : 0.f;
        float vx0 = (x0 >= 0 && x0 < W) ? 1.f : 0.f;
        float vx1 = (x1 >= 0 && x1 < W) ? 1.f : 0.f;

        float w00 = mw * (1.f - tyf) * (1.f - txf) * vy0 * vx0;
        float w01 = mw * (1.f - tyf) * txf * vy0 * vx1;
        float w10 = mw * tyf * (1.f - txf) * vy1 * vx0;
        float w11 = mw * tyf * txf * vy1 * vx1;

        int y0c = min(max(y0, 0), H - 1);
        int y1c = min(max(y1, 0), H - 1);
        int x0c = min(max(x0, 0), W - 1);
        int x1c = min(max(x1, 0), W - 1);

        int yA = y0c << 12, yB = y1c << 12;
        int xA = x0c << 6,  xB = x1c << 6;

        ulonglong2 v00 = __ldg(vp + (yA + xA));
        ulonglong2 v01 = __ldg(vp + (yA + xB));
        ulonglong2 v10 = __ldg(vp + (yB + xA));
        ulonglong2 v11 = __ldg(vp + (yB + xB));

        uint64_t w00p = dup2(w00), w01p = dup2(w01);
        uint64_t w10p = dup2(w10), w11p = dup2(w11);

        fma2(acc0, w00p, v00.x);
        fma2(acc1, w00p, v00.y);
        fma2(acc0, w01p, v01.x);
        fma2(acc1, w01p, v01.y);
        fma2(acc0, w10p, v10.x);
        fma2(acc1, w10p, v10.y);
        fma2(acc0, w11p, v11.x);
        fma2(acc1, w11p, v11.y);
    }

    float2 a01 = unpack2(acc0);
    float2 a23 = unpack2(acc1);
    __nv_bfloat16 h0, l0b, h1, l1b, h2, l2b, h3, l3b;
    bsplit(a01.x, h0, l0b);
    bsplit(a01.y, h1, l1b);
    bsplit(a23.x, h2, l2b);
    bsplit(a23.y, h3, l3b);
    uint2 hv = make_uint2(packbf(h0, h1), packbf(h2, h3));
    uint2 lv = make_uint2(packbf(l0b, l1b), packbf(l2b, l3b));

    char* ob = (char*)(g_aop + ((size_t)(n * L + l)) * KA) + (g * 32 + c4 * 4) * 2;
    *(uint2*)(ob)       = hv;     // hi @ elems [0,256)
    *(uint2*)(ob + 512) = lv;     // lo @ elems [256,512)
}

// ---------------------------------------------------------------------------
// Launch
// ---------------------------------------------------------------------------
extern "C" void kernel_launch(void* const* d_in, const int* in_sizes, int n_in,
                              void* d_out, int out_size) {
    const float* x    = (const float*)d_in[0];
    const float* dw_w = (const float*)d_in[1];
    const float* dw_b = (const float*)d_in[2];
    const float* om_w = (const float*)d_in[3];
    const float* om_b = (const float*)d_in[4];
    const float* vp_w = (const float*)d_in[5];
    const float* vp_b = (const float*)d_in[6];
    const float* op_w = (const float*)d_in[7];
    float* out = (float*)d_out;

    float *p_value, *p_om_p, *p_bias_om;
    __nv_bfloat16 *p_aval, *p_aom, *p_aop, *p_bw;
    cudaGetSymbolAddress((void**)&p_value, g_value);
    cudaGetSymbolAddress((void**)&p_om_p, g_om_p);
    cudaGetSymbolAddress((void**)&p_bias_om, g_bias_om);
    cudaGetSymbolAddress((void**)&p_aval, g_aval);
    cudaGetSymbolAddress((void**)&p_aom, g_aom);
    cudaGetSymbolAddress((void**)&p_aop, g_aop);
    cudaGetSymbolAddress((void**)&p_bw, g_bw);

    cudaFuncSetAttribute(gemm_mma_kernel,
                         cudaFuncAttributeMaxDynamicSharedMemorySize, SMEM_GEMM);

    prep_w_kernel<<<dim3(256, 3), 256>>>(om_w, om_b, vp_w, op_w);
    convT_kernel<<<dim3(L / 256, 4, NB), 256>>>(x, p_aval);
    convT_om_kernel<<<dim3(L / 256, 4, NB), 256>>>(x, dw_w, dw_b, p_aom);
    gemm_mma_kernel<<<dim3(1, 32, NB), 256, SMEM_GEMM>>>(p_aom, p_bw, p_bias_om, p_om_p, 0);
    gemm_mma_kernel<<<dim3(1, 32, NB), 256, SMEM_GEMM>>>(p_aval, p_bw + (size_t)256 * KA, vp_b, p_value, 0);
    sample_kernel<<<dim3(L / 32, G, NB), 256>>>();
    gemm_mma_kernel<<<dim3(1, 32, NB), 256, SMEM_GEMM>>>(p_aop, p_bw + (size_t)2 * 256 * KA, p_bias_om, out, 1);
}

// round 14
// speedup vs baseline: 1.1035x; 1.0673x over previous
#include <cuda_runtime.h>
#include <cuda_bf16.h>
#include <cstdint>

// Problem constants
#define NB  8
#define C   256
#define G   8
#define KPT 9
#define H   64
#define W   64
#define L   (H * W)          // 4096
#define CG  (C / G)          // 32
#define KA  512              // stored K: A=[hi|lo], B=[hi|lo]; GEMM runs K=768 via remap

// Scratch (static device memory)
__device__ float g_value[(size_t)NB * L * C];               // value proj (n,l,256) f32
__device__ float g_om_p[(size_t)NB * L * C];                // om padded (n,l,256) f32
__device__ __nv_bfloat16 g_aval[(size_t)NB * L * KA];       // A' for value GEMM
__device__ __nv_bfloat16 g_aom[(size_t)NB * L * KA];        // A' for om GEMM
__device__ __nv_bfloat16 g_aop[(size_t)NB * L * KA];        // A' for out GEMM
__device__ __nv_bfloat16 g_bw[3 * 256 * KA];                // B' weights (om, vp, op)
__device__ float g_bias_om[256];                            // padded om bias

// ---------------- small helpers ----------------
__device__ __forceinline__ uint32_t smem_u32(const void* p) {
    uint32_t a;
    asm("{ .reg .u64 t; cvta.to.shared.u64 t, %1; cvt.u32.u64 %0, t; }" : "=r"(a) : "l"(p));
    return a;
}
__device__ __forceinline__ void fma2(uint64_t& d, uint64_t a, uint64_t b) {
    asm("fma.rn.f32x2 %0, %1, %2, %0;" : "+l"(d) : "l"(a), "l"(b));
}
__device__ __forceinline__ uint64_t dup2(float a) {
    uint64_t r;
    asm("mov.b64 %0, {%1, %1};" : "=l"(r) : "f"(a));
    return r;
}
__device__ __forceinline__ float2 unpack2(uint64_t v) {
    float2 r;
    asm("mov.b64 {%0, %1}, %2;" : "=f"(r.x), "=f"(r.y) : "l"(v));
    return r;
}
__device__ __forceinline__ uint32_t packbf(__nv_bfloat16 lo, __nv_bfloat16 hi) {
    __nv_bfloat162 t;
    t.x = lo; t.y = hi;
    return *(uint32_t*)&t;
}
__device__ __forceinline__ void bsplit(float v, __nv_bfloat16& h, __nv_bfloat16& l) {
    h = __float2bfloat16(v);
    l = __float2bfloat16(v - __bfloat162float(h));
}

// ---- warp mma primitives (sm_80-compatible; legal under compute_103) ------
__device__ __forceinline__ void ldmatrix_x4(uint32_t& r0, uint32_t& r1,
                                            uint32_t& r2, uint32_t& r3,
                                            uint32_t addr) {
    asm volatile("ldmatrix.sync.aligned.m8n8.x4.shared.b16 {%0,%1,%2,%3}, [%4];"
                 : "=r"(r0), "=r"(r1), "=r"(r2), "=r"(r3) : "r"(addr));
}
__device__ __forceinline__ void mma16816(float* d, const uint32_t* a,
                                         const uint32_t* b) {
    asm volatile(
        "mma.sync.aligned.m16n8k16.row.col.f32.bf16.bf16.f32 "
        "{%0,%1,%2,%3}, {%4,%5,%6,%7}, {%8,%9}, {%0,%1,%2,%3};"
        : "+f"(d[0]), "+f"(d[1]), "+f"(d[2]), "+f"(d[3])
        : "r"(a[0]), "r"(a[1]), "r"(a[2]), "r"(a[3]), "r"(b[0]), "r"(b[1]));
}
__device__ __forceinline__ void cp16(uint32_t saddr, const void* g) {
    asm volatile("cp.async.cg.shared.global [%0], [%1], 16;" :: "r"(saddr), "l"(g));
}
__device__ __forceinline__ void cp_commit() {
    asm volatile("cp.async.commit_group;" ::: "memory");
}
template <int N>
__device__ __forceinline__ void cp_wait() {
    asm volatile("cp.async.wait_group %0;" :: "n"(N) : "memory");
}

// ---------------------------------------------------------------------------
// Weight prep: Wsrc (J,256) f32 -> B' (256 rows, 512) bf16 [hi | lo]
// ---------------------------------------------------------------------------
__global__ __launch_bounds__(256) void prep_w_kernel(const float* __restrict__ om_w,
                                                     const float* __restrict__ om_b,
                                                     const float* __restrict__ vp_w,
                                                     const float* __restrict__ op_w) {
    int j = blockIdx.x;
    int ws = blockIdx.y;
    int c = threadIdx.x;
    const float* Wsrc = (ws == 0) ? om_w : (ws == 1) ? vp_w : op_w;
    int Jrows = (ws == 0) ? 216 : 256;
    float v = (j < Jrows) ? Wsrc[j * 256 + c] : 0.f;
    __nv_bfloat16 h, lo;
    bsplit(v, h, lo);
    __nv_bfloat16* outw = g_bw + ((size_t)ws * 256 + j) * KA;
    outw[c] = h;
    outw[256 + c] = lo;
    if (ws == 0 && j == 0)
        g_bias_om[c] = (c < 216) ? om_b[c] : 0.f;
}

// ---------------------------------------------------------------------------
// Transpose-convert: X (n, 256, L) f32 -> A' (n, L, 512) bf16 [hi | lo]
// grid (L/256, 4, NB)
// ---------------------------------------------------------------------------
__global__ __launch_bounds__(256) void convT_kernel(const float* __restrict__ X,
                                                    __nv_bfloat16* __restrict__ Ab) {
    int l = blockIdx.x * 256 + threadIdx.x;
    int c80 = blockIdx.y * 8;
    int n = blockIdx.z;
    const float* xp = X + ((size_t)n * 256) * L + l;
    char* ob = (char*)(Ab + ((size_t)(n * L + l)) * KA);
#pragma unroll
    for (int c8 = c80; c8 < c80 + 8; c8++) {
        uint32_t hi[4], lw[4];
#pragma unroll
        for (int j = 0; j < 4; j++) {
            float a = xp[(size_t)(c8 * 8 + 2 * j) * L];
            float b = xp[(size_t)(c8 * 8 + 2 * j + 1) * L];
            __nv_bfloat16 ha, la, hb, lb;
            bsplit(a, ha, la);
            bsplit(b, hb, lb);
            hi[j] = packbf(ha, hb);
            lw[j] = packbf(la, lb);
        }
        *(uint4*)(ob + c8 * 16)       = make_uint4(hi[0], hi[1], hi[2], hi[3]);
        *(uint4*)(ob + 512 + c8 * 16) = make_uint4(lw[0], lw[1], lw[2], lw[3]);
    }
}

// ---------------------------------------------------------------------------
// Fused depthwise-conv + transpose-convert for the om path.
// grid (L/256, 4, NB)
// ---------------------------------------------------------------------------
__global__ __launch_bounds__(256) void convT_om_kernel(const float* __restrict__ x,
                                                       const float* __restrict__ dw,
                                                       const float* __restrict__ db,
                                                       __nv_bfloat16* __restrict__ Ab) {
    int l = blockIdx.x * 256 + threadIdx.x;
    int c80 = blockIdx.y * 8;
    int n = blockIdx.z;
    int yy = l >> 6, xx = l & 63;

    int offs[9];
    float val9[9];
#pragma unroll
    for (int t = 0; t < 9; t++) {
        int dy = t / 3 - 1, dx = t % 3 - 1;
        int y2 = yy + dy, x2 = xx + dx;
        bool v = (y2 >= 0 && y2 < H && x2 >= 0 && x2 < W);
        offs[t] = v ? (y2 * W + x2) : 0;
        val9[t] = v ? 1.f : 0.f;
    }

    const float* xb = x + ((size_t)n * 256) * L;
    char* ob = (char*)(Ab + ((size_t)(n * L + l)) * KA);

#pragma unroll
    for (int c8 = c80; c8 < c80 + 8; c8++) {
        uint32_t hi[4], lw[4];
#pragma unroll
        for (int j = 0; j < 4; j++) {
            float r[2];
#pragma unroll
            for (int s = 0; s < 2; s++) {
                int c = c8 * 8 + 2 * j + s;
                const float* xc = xb + (size_t)c * L;
                const float* wc = dw + c * 9;
                float acc = db[c];
#pragma unroll
                for (int t = 0; t < 9; t++)
                    acc += wc[t] * val9[t] * xc[offs[t]];
                r[s] = acc;
            }
            __nv_bfloat16 ha, la, hb, lb;
            bsplit(r[0], ha, la);
            bsplit(r[1], hb, lb);
            hi[j] = packbf(ha, hb);
            lw[j] = packbf(la, lb);
        }
        *(uint4*)(ob + c8 * 16)       = make_uint4(hi[0], hi[1], hi[2], hi[3]);
        *(uint4*)(ob + 512 + c8 * 16) = make_uint4(lw[0], lw[1], lw[2], lw[3]);
    }
}

// ---------------------------------------------------------------------------
// Warp-mma bf16 GEMM, v4: R8 shape (CTA 128x128, 8 warps, 64x32 warp tiles)
// + 4-stage cp.async (depth-3 prefetch), one __syncthreads per kc.
// Split remap: storage K=512; logical K=768:
//   kc<8: ah*bh | 8..15: al*bh | 16..23: ah*bl.
// grid (2, 32, NB).
// mode 0: out row-major (n, L, 256) f32 + bias;  mode 1: NCHW, no bias.
// ---------------------------------------------------------------------------
#define BK 32
#define ASTR 40              // padded smem row stride (bf16 units)
#define NKC 24
#define STG 4
#define TILEB (128 * ASTR * 2)           // 10240 B per tile
#define SMEM_GEMM (STG * 2 * TILEB)      // 81920 B

__device__ __forceinline__ int a_seg(int kc) {
    return (kc < 8) ? kc * BK : (kc < 16) ? 256 + (kc - 8) * BK : (kc - 16) * BK;
}
__device__ __forceinline__ int b_seg(int kc) {
    return (kc < 16) ? (kc & 7) * BK : 256 + (kc - 16) * BK;
}

__global__ __launch_bounds__(256)
void gemm_mma_kernel(const __nv_bfloat16* __restrict__ Ab,
                     const __nv_bfloat16* __restrict__ Bb,
                     const float* __restrict__ bias,
                     float* __restrict__ outp,
                     int mode) {
    extern __shared__ char sm[];
    uint32_t s0 = smem_u32(sm);

    int tid = threadIdx.x;
    int lane = tid & 31;
    int wid = tid >> 5;
    int warp_m = wid >> 2;       // 0..1
    int warp_n = wid & 3;        // 0..3
    int n0 = blockIdx.x * 128;
    int m0 = blockIdx.y * 128;
    int n  = blockIdx.z;

    // loader mapping: row = tid>>1 (128 rows), 32B seg = (tid&1)*32
    const char* AgL = (const char*)(Ab + ((size_t)(n * L + m0) + (tid >> 1)) * KA) + (tid & 1) * 32;
    const char* BgL = (const char*)(Bb + ((size_t)n0 + (tid >> 1)) * KA) + (tid & 1) * 32;

    uint32_t sA[STG], sB[STG];
#pragma unroll
    for (int s = 0; s < STG; s++) {
        sA[s] = s0 + s * TILEB;
        sB[s] = s0 + STG * TILEB + s * TILEB;
    }
    uint32_t srow = (tid >> 1) * (ASTR * 2) + (tid & 1) * 32;

    float d[4][4][4];
#pragma unroll
    for (int i = 0; i < 4; i++)
#pragma unroll
        for (int j = 0; j < 4; j++)
#pragma unroll
            for (int k = 0; k < 4; k++) d[i][j][k] = 0.f;

    auto issue = [&](int kc, int s) {
        int ao = a_seg(kc) * 2, bo = b_seg(kc) * 2;   // byte offsets
        cp16(sA[s] + srow,      AgL + ao);
        cp16(sA[s] + srow + 16, AgL + ao + 16);
        cp16(sB[s] + srow,      BgL + bo);
        cp16(sB[s] + srow + 16, BgL + bo + 16);
        cp_commit();
    };

    issue(0, 0);
    issue(1, 1);
    issue(2, 2);

    int a_rbase = warp_m * 64 + (lane & 15);
    int a_kbase = (lane >> 4) << 3;
    // B fragment mapping for ldmatrix_x4 covering 2 n-tiles x 2 k-halves
    int b_rbase = warp_n * 32 + (((lane >> 4) & 1) << 3) + (lane & 7);
    int b_kbase = ((lane >> 3) & 1) << 3;

    for (int kc = 0; kc < NKC; kc++) {
        cp_wait<2>();
        __syncthreads();
        int buf = kc % STG;
        if (kc + 3 < NKC) issue(kc + 3, (kc + 3) % STG);

#pragma unroll
        for (int kk = 0; kk < 2; kk++) {
            uint32_t b[4][2];
#pragma unroll
            for (int ntp = 0; ntp < 2; ntp++) {
                uint32_t addr = sB[buf] +
                    ((b_rbase + ntp * 16) * ASTR + kk * 16 + b_kbase) * 2;
                ldmatrix_x4(b[2 * ntp][0], b[2 * ntp][1],
                            b[2 * ntp + 1][0], b[2 * ntp + 1][1], addr);
            }
#pragma unroll
            for (int mt = 0; mt < 4; mt++) {
                uint32_t a[4];
                uint32_t addr = sA[buf] +
                    ((a_rbase + mt * 16) * ASTR + kk * 16 + a_kbase) * 2;
                ldmatrix_x4(a[0], a[1], a[2], a[3], addr);
#pragma unroll
                for (int nt = 0; nt < 4; nt++)
                    mma16816(d[mt][nt], a, b[nt]);
            }
        }
    }

    // epilogue
    int rbase = m0 + warp_m * 64 + (lane >> 2);
    int cbase = n0 + warp_n * 32 + (lane & 3) * 2;
    if (mode == 0) {
        float* ob = outp + (size_t)n * L * 256;
#pragma unroll
        for (int mt = 0; mt < 4; mt++) {
#pragma unroll
            for (int nt = 0; nt < 4; nt++) {
                int r = rbase + mt * 16;
                int c = cbase + nt * 8;
                float bx = __ldg(bias + c), by = __ldg(bias + c + 1);
                *(float2*)(ob + (size_t)r * 256 + c) =
                    make_float2(d[mt][nt][0] + bx, d[mt][nt][1] + by);
                *(float2*)(ob + (size_t)(r + 8) * 256 + c) =
                    make_float2(d[mt][nt][2] + bx, d[mt][nt][3] + by);
            }
        }
    } else {
        float* ob = outp + (size_t)n * 256 * L;
#pragma unroll
        for (int mt = 0; mt < 4; mt++) {
#pragma unroll
            for (int nt = 0; nt < 4; nt++) {
                int r = rbase + mt * 16;
                int c = cbase + nt * 8;
                float* p0 = ob + (size_t)c * L;
                float* p1 = ob + (size_t)(c + 1) * L;
                p0[r] = d[mt][nt][0];
                p1[r] = d[mt][nt][1];
                p0[r + 8] = d[mt][nt][2];
                p1[r + 8] = d[mt][nt][3];
            }
        }
    }
}

// ---------------------------------------------------------------------------
// Deformable bilinear sampling; emits split-bf16 A' [hi | lo] for out GEMM.
// ---------------------------------------------------------------------------
__global__ __launch_bounds__(256) void sample_kernel() {
    __shared__ float om_s[32][28];

    int tid = threadIdx.x;
    int c4 = tid & 7;
    int li = tid >> 3;
    int l0 = blockIdx.x * 32;
    int g  = blockIdx.y;
    int n  = blockIdx.z;

    for (int i = tid; i < 32 * 27; i += 256) {
        int li2 = i / 27, j = i - li2 * 27;
        om_s[li2][j] = g_om_p[(size_t)(n * L + l0 + li2) * 256 + g * 27 + j];
    }
    __syncthreads();

    int l = l0 + li;
    int yy = l >> 6, xx = l & 63;

    const ulonglong2* __restrict__ vp =
        (const ulonglong2*)(g_value + (size_t)n * L * C + g * CG) + c4;
    const float fyy = (float)yy, fxx = (float)xx;

    uint64_t acc0 = 0ull, acc1 = 0ull;

#pragma unroll
    for (int k = 0; k < KPT; k++) {
        float oy = om_s[li][2 * k];
        float ox = om_s[li][2 * k + 1];
        float mw = om_s[li][18 + k];

        float py = fyy + (float)(k / 3 - 1) + oy;
        float px = fxx + (float)(k % 3 - 1) + ox;
        float y0f = floorf(py), x0f = floorf(px);
        float tyf = py - y0f, txf = px - x0f;
        int y0 = (int)y0f, x0 = (int)x0f;
        int y1 = y0 + 1, x1 = x0 + 1;

        float vy0 = (y0 >= 0 && y0 < H) ? 1.f : 0.f;
        float vy1 = (y1 >= 0 && y1 < H) ? 1.f : 0.f;
        float vx0 = (x0 >= 0 && x0 < W) ? 1.f : 0.f;
        float vx1 = (x1 >= 0 && x1 < W) ? 1.f : 0.f;

        float w00 = mw * (1.f - tyf) * (1.f - txf) * vy0 * vx0;
        float w01 = mw * (1.f - tyf) * txf * vy0 * vx1;
        float w10 = mw * tyf * (1.f - txf) * vy1 * vx0;
        float w11 = mw * tyf * txf * vy1 * vx1;

        int y0c = min(max(y0, 0), H - 1);
        int y1c = min(max(y1, 0), H - 1);
        int x0c = min(max(x0, 0), W - 1);
        int x1c = min(max(x1, 0), W - 1);

        int yA = y0c << 12, yB = y1c << 12;
        int xA = x0c << 6,  xB = x1c << 6;

        ulonglong2 v00 = __ldg(vp + (yA + xA));
        ulonglong2 v01 = __ldg(vp + (yA + xB));
        ulonglong2 v10 = __ldg(vp + (yB + xA));
        ulonglong2 v11 = __ldg(vp + (yB + xB));

        uint64_t w00p = dup2(w00), w01p = dup2(w01);
        uint64_t w10p = dup2(w10), w11p = dup2(w11);

        fma2(acc0, w00p, v00.x);
        fma2(acc1, w00p, v00.y);
        fma2(acc0, w01p, v01.x);
        fma2(acc1, w01p, v01.y);
        fma2(acc0, w10p, v10.x);
        fma2(acc1, w10p, v10.y);
        fma2(acc0, w11p, v11.x);
        fma2(acc1, w11p, v11.y);
    }

    float2 a01 = unpack2(acc0);
    float2 a23 = unpack2(acc1);
    __nv_bfloat16 h0, l0b, h1, l1b, h2, l2b, h3, l3b;
    bsplit(a01.x, h0, l0b);
    bsplit(a01.y, h1, l1b);
    bsplit(a23.x, h2, l2b);
    bsplit(a23.y, h3, l3b);
    uint2 hv = make_uint2(packbf(h0, h1), packbf(h2, h3));
    uint2 lv = make_uint2(packbf(l0b, l1b), packbf(l2b, l3b));

    char* ob = (char*)(g_aop + ((size_t)(n * L + l)) * KA) + (g * 32 + c4 * 4) * 2;
    *(uint2*)(ob)       = hv;     // hi @ elems [0,256)
    *(uint2*)(ob + 512) = lv;     // lo @ elems [256,512)
}

// ---------------------------------------------------------------------------
// Launch
// ---------------------------------------------------------------------------
extern "C" void kernel_launch(void* const* d_in, const int* in_sizes, int n_in,
                              void* d_out, int out_size) {
    const float* x    = (const float*)d_in[0];
    const float* dw_w = (const float*)d_in[1];
    const float* dw_b = (const float*)d_in[2];
    const float* om_w = (const float*)d_in[3];
    const float* om_b = (const float*)d_in[4];
    const float* vp_w = (const float*)d_in[5];
    const float* vp_b = (const float*)d_in[6];
    const float* op_w = (const float*)d_in[7];
    float* out = (float*)d_out;

    float *p_value, *p_om_p, *p_bias_om;
    __nv_bfloat16 *p_aval, *p_aom, *p_aop, *p_bw;
    cudaGetSymbolAddress((void**)&p_value, g_value);
    cudaGetSymbolAddress((void**)&p_om_p, g_om_p);
    cudaGetSymbolAddress((void**)&p_bias_om, g_bias_om);
    cudaGetSymbolAddress((void**)&p_aval, g_aval);
    cudaGetSymbolAddress((void**)&p_aom, g_aom);
    cudaGetSymbolAddress((void**)&p_aop, g_aop);
    cudaGetSymbolAddress((void**)&p_bw, g_bw);

    cudaFuncSetAttribute(gemm_mma_kernel,
                         cudaFuncAttributeMaxDynamicSharedMemorySize, SMEM_GEMM);

    prep_w_kernel<<<dim3(256, 3), 256>>>(om_w, om_b, vp_w, op_w);
    convT_kernel<<<dim3(L / 256, 4, NB), 256>>>(x, p_aval);
    convT_om_kernel<<<dim3(L / 256, 4, NB), 256>>>(x, dw_w, dw_b, p_aom);
    gemm_mma_kernel<<<dim3(2, 32, NB), 256, SMEM_GEMM>>>(p_aom, p_bw, p_bias_om, p_om_p, 0);
    gemm_mma_kernel<<<dim3(2, 32, NB), 256, SMEM_GEMM>>>(p_aval, p_bw + (size_t)256 * KA, vp_b, p_value, 0);
    sample_kernel<<<dim3(L / 32, G, NB), 256>>>();
    gemm_mma_kernel<<<dim3(2, 32, NB), 256, SMEM_GEMM>>>(p_aop, p_bw + (size_t)2 * 256 * KA, p_bias_om, out, 1);
}